// round 2
// baseline (speedup 1.0000x reference)
#include <cuda_runtime.h>
#include <cstdint>

#define NN 8192
#define DD 128
#define KNN 20
#define NC 10
#define NW 256   // 32-bit words per mask row (8192/32)

// ---------------- scratch (device globals; no allocations) ----------------
__device__ float        g_dist[(size_t)NN * NN];   // 256 MB distance matrix
__device__ float        g_sq[NN];
__device__ float        g_density[NN];
__device__ unsigned int g_mask[(size_t)NN * NW];   // kmask | kmask^T as bits

// ---------------- kernel 1: zero the mask ----------------
__global__ void zero_mask_kernel() {
    int i = blockIdx.x * blockDim.x + threadIdx.x;
    if (i < NN * NW) g_mask[i] = 0u;
}

// ---------------- kernel 2: row squared norms ----------------
__global__ void norms_kernel(const float* __restrict__ X) {
    int row  = blockIdx.x * 8 + (threadIdx.x >> 5);
    int lane = threadIdx.x & 31;
    const float4* xr = (const float4*)(X + (size_t)row * DD);
    float4 v = xr[lane];                       // 32 lanes * 4 = 128
    float s = v.x * v.x + v.y * v.y + v.z * v.z + v.w * v.w;
#pragma unroll
    for (int o = 16; o; o >>= 1) s += __shfl_xor_sync(0xffffffffu, s, o);
    if (lane == 0) g_sq[row] = s;
}

// ---------------- kernel 3: symmetric tiled distance matrix ----------------
// 64x64 tile per block, 256 threads, 4x4 microtile, K chunks of 32.
// Computes only bi <= bj; mirrors the tile through shared memory.
__global__ __launch_bounds__(256) void dist_kernel(const float* __restrict__ X) {
    int bi = blockIdx.y, bj = blockIdx.x;
    if (bj < bi) return;

    __shared__ float smem[2 * 64 * 33];        // As[64][33] then Bs[64][33]
    float* As = smem;
    float* Bs = smem + 64 * 33;

    int tid = threadIdx.x;
    int tx = tid & 15, ty = tid >> 4;

    float acc[4][4];
#pragma unroll
    for (int a = 0; a < 4; a++)
#pragma unroll
        for (int b = 0; b < 4; b++) acc[a][b] = 0.f;

    const float* Arow = X + (size_t)(bi * 64) * DD;
    const float* Brow = X + (size_t)(bj * 64) * DD;

    for (int kb = 0; kb < DD; kb += 32) {
#pragma unroll
        for (int u = 0; u < 2; u++) {
            int f  = tid + u * 256;            // 512 float4 loads per tile
            int r  = f >> 3;
            int c4 = (f & 7) * 4;
            float4 va = *(const float4*)(Arow + (size_t)r * DD + kb + c4);
            As[r * 33 + c4 + 0] = va.x; As[r * 33 + c4 + 1] = va.y;
            As[r * 33 + c4 + 2] = va.z; As[r * 33 + c4 + 3] = va.w;
            float4 vb = *(const float4*)(Brow + (size_t)r * DD + kb + c4);
            Bs[r * 33 + c4 + 0] = vb.x; Bs[r * 33 + c4 + 1] = vb.y;
            Bs[r * 33 + c4 + 2] = vb.z; Bs[r * 33 + c4 + 3] = vb.w;
        }
        __syncthreads();
#pragma unroll
        for (int k = 0; k < 32; k++) {
            float a0 = As[(ty +  0) * 33 + k];
            float a1 = As[(ty + 16) * 33 + k];
            float a2 = As[(ty + 32) * 33 + k];
            float a3 = As[(ty + 48) * 33 + k];
            float b0 = Bs[(tx +  0) * 33 + k];
            float b1 = Bs[(tx + 16) * 33 + k];
            float b2 = Bs[(tx + 32) * 33 + k];
            float b3 = Bs[(tx + 48) * 33 + k];
            acc[0][0] += a0 * b0; acc[0][1] += a0 * b1; acc[0][2] += a0 * b2; acc[0][3] += a0 * b3;
            acc[1][0] += a1 * b0; acc[1][1] += a1 * b1; acc[1][2] += a1 * b2; acc[1][3] += a1 * b3;
            acc[2][0] += a2 * b0; acc[2][1] += a2 * b1; acc[2][2] += a2 * b2; acc[2][3] += a2 * b3;
            acc[3][0] += a3 * b0; acc[3][1] += a3 * b1; acc[3][2] += a3 * b2; acc[3][3] += a3 * b3;
        }
        __syncthreads();
    }

    float sa[4], sb[4];
#pragma unroll
    for (int a = 0; a < 4; a++) sa[a] = g_sq[bi * 64 + ty + 16 * a];
#pragma unroll
    for (int b = 0; b < 4; b++) sb[b] = g_sq[bj * 64 + tx + 16 * b];

#pragma unroll
    for (int a = 0; a < 4; a++) {
        int R = bi * 64 + ty + 16 * a;
#pragma unroll
        for (int b = 0; b < 4; b++) {
            int Cc = bj * 64 + tx + 16 * b;
            float d2 = sa[a] + sb[b] - 2.f * acc[a][b];
            float dd = sqrtf(fmaxf(d2, 0.f));
            g_dist[(size_t)R * NN + Cc] = dd;
            acc[a][b] = dd;                    // keep for mirror
        }
    }

    if (bi != bj) {
        __syncthreads();
        float* T = smem;                       // 64*65 = 4160 <= 4224 floats
#pragma unroll
        for (int a = 0; a < 4; a++)
#pragma unroll
            for (int b = 0; b < 4; b++)
                T[(tx + 16 * b) * 65 + (ty + 16 * a)] = acc[a][b];
        __syncthreads();
#pragma unroll
        for (int a = 0; a < 4; a++) {
            int R = bj * 64 + ty + 16 * a;
#pragma unroll
            for (int b = 0; b < 4; b++) {
                int Cc = bi * 64 + tx + 16 * b;
                g_dist[(size_t)R * NN + Cc] = T[(ty + 16 * a) * 65 + (tx + 16 * b)];
            }
        }
    }
}

// ---------------- kernel 4: per-row top-K (smallest, tie -> lower index) ---
__global__ __launch_bounds__(256) void topk_kernel() {
    int i    = blockIdx.x;
    int tid  = threadIdx.x;
    int lane = tid & 31;
    int wid  = tid >> 5;

    __shared__ float sd[NN];                   // 32 KB row copy
    __shared__ unsigned long long wmin[8];
    __shared__ float s_ksum;

    const float* row = g_dist + (size_t)i * NN;
    for (int j = tid; j < NN; j += 256) sd[j] = row[j];
    __syncthreads();

    // thread owns indices tid + 256*u (conflict-free shared access)
    unsigned long long cur = 0xFFFFFFFFFFFFFFFFull;
#pragma unroll
    for (int u = 0; u < 32; u++) {
        int j = tid + 256 * u;
        unsigned long long key =
            ((unsigned long long)__float_as_uint(sd[j]) << 32) | (unsigned)j;
        cur = (key < cur) ? key : cur;
    }

    if (tid == 0) s_ksum = 0.f;
    __syncthreads();

    for (int t = 0; t < KNN; t++) {
        unsigned long long w = cur;
#pragma unroll
        for (int o = 16; o; o >>= 1) {
            unsigned long long other = __shfl_xor_sync(0xffffffffu, w, o);
            w = (other < w) ? other : w;
        }
        if (lane == 0) wmin[wid] = w;
        __syncthreads();
        if (tid == 0) {
            unsigned long long g = wmin[0];
#pragma unroll
            for (int q = 1; q < 8; q++) g = (wmin[q] < g) ? wmin[q] : g;
            wmin[0] = g;
        }
        __syncthreads();
        unsigned long long g = wmin[0];
        int   idx = (int)(g & 0xFFFFFFFFull);
        float val = __uint_as_float((unsigned)(g >> 32));

        if (tid == (idx & 255)) {              // owner invalidates + rescans
            sd[idx] = __int_as_float(0x7f800000);
            unsigned long long nm = 0xFFFFFFFFFFFFFFFFull;
#pragma unroll
            for (int u = 0; u < 32; u++) {
                int j = tid + 256 * u;
                unsigned long long key =
                    ((unsigned long long)__float_as_uint(sd[j]) << 32) | (unsigned)j;
                nm = (key < nm) ? key : nm;
            }
            cur = nm;
        }
        if (tid == 0) {
            s_ksum += val;
            atomicOr(&g_mask[(size_t)i * NW + (idx >> 5)], 1u << (idx & 31));
            atomicOr(&g_mask[(size_t)idx * NW + (i >> 5)], 1u << (i & 31));
        }
        __syncthreads();
    }
    if (tid == 0)
        g_density[i] = 1.0f / (s_ksum / (float)KNN + 1e-10f);
}

// ---------------- kernel 5: influence average + score + classify ----------
__global__ void final_kernel(const float* __restrict__ logits,
                             float* __restrict__ out, int out_size) {
    int row  = blockIdx.x * 8 + (threadIdx.x >> 5);
    int lane = threadIdx.x & 31;
    const unsigned int* mr = g_mask + (size_t)row * NW;

    float s = 0.f;
    int cnt = 0;
#pragma unroll
    for (int u = 0; u < 8; u++) {
        int w = lane + 32 * u;
        unsigned int bits = mr[w];
        cnt += __popc(bits);
        while (bits) {
            int b = __ffs(bits) - 1;
            bits &= bits - 1;
            s += g_density[w * 32 + b];
        }
    }
#pragma unroll
    for (int o = 16; o; o >>= 1) {
        s   += __shfl_xor_sync(0xffffffffu, s, o);
        cnt += __shfl_xor_sync(0xffffffffu, cnt, o);
    }
    if (lane == 0) {
        float den   = g_density[row];
        float avg   = s / (float)(cnt > 0 ? cnt : 1);
        float score = -(den / (avg + 1e-10f));
        out[row] = score;
        bool flag = score < -0.5f;
        if (out_size >= 2 * NN) out[NN + row] = flag ? 1.f : 0.f;
        if (out_size >= 3 * NN) {
            int pred = -1;
            if (!flag) {
                const float* lg = logits + (size_t)row * NC;
                float best = lg[0]; pred = 0;
#pragma unroll
                for (int c = 1; c < NC; c++)
                    if (lg[c] > best) { best = lg[c]; pred = c; }
            }
            out[2 * NN + row] = (float)pred;
        }
    }
}

// ---------------- launch ----------------
extern "C" void kernel_launch(void* const* d_in, const int* in_sizes, int n_in,
                              void* d_out, int out_size) {
    (void)in_sizes; (void)n_in;
    const float* X = (const float*)d_in[0];   // embeddings [8192,128] f32
    const float* L = (const float*)d_in[1];   // logits     [8192,10]  f32
    float* out = (float*)d_out;

    zero_mask_kernel<<<(NN * NW + 255) / 256, 256>>>();
    norms_kernel<<<NN / 8, 256>>>(X);
    dim3 g(NN / 64, NN / 64);
    dist_kernel<<<g, 256>>>(X);
    topk_kernel<<<NN, 256>>>();
    final_kernel<<<NN / 8, 256>>>(L, out, out_size);
}

// round 3
// speedup vs baseline: 1.1937x; 1.1937x over previous
#include <cuda_runtime.h>
#include <cstdint>

#define NN 8192
#define DD 128
#define KNN 20
#define NC 10
#define NW 256    // 32-bit words per mask row
#define HB 2048   // histogram bins (float bits >> 20)
#define BCAP 256  // boundary-bin candidate capacity

// ---------------- scratch (device globals; no allocations) ----------------
__device__ float        g_dist[(size_t)NN * NN];   // squared distances (clamped >= 0)
__device__ float        g_sq[NN];
__device__ float        g_density[NN];
__device__ unsigned int g_mask[(size_t)NN * NW];   // kmask | kmask^T

// ---------------- kernel 1: zero the mask ----------------
__global__ void zero_mask_kernel() {
    int i = blockIdx.x * blockDim.x + threadIdx.x;
    if (i < NN * NW) g_mask[i] = 0u;
}

// ---------------- kernel 2: row squared norms ----------------
__global__ void norms_kernel(const float* __restrict__ X) {
    int row  = blockIdx.x * 8 + (threadIdx.x >> 5);
    int lane = threadIdx.x & 31;
    const float4* xr = (const float4*)(X + (size_t)row * DD);
    float4 v = xr[lane];
    float s = v.x * v.x + v.y * v.y + v.z * v.z + v.w * v.w;
#pragma unroll
    for (int o = 16; o; o >>= 1) s += __shfl_xor_sync(0xffffffffu, s, o);
    if (lane == 0) g_sq[row] = s;
}

// ---------------- kernel 3: symmetric tiled squared-distance matrix -------
// 64x64 tile, 256 threads, 4x4 contiguous microtile. Smem tiles stored
// TRANSPOSED ([k][row], stride 68 for 16B-aligned float4 reads) so the
// inner loop does 2 x LDS.128 per k-step instead of 8 scalar LDS.
// Stores d^2 (no sqrt). Mirrors the tile via a smem transpose buffer.
__global__ __launch_bounds__(256) void dist_kernel(const float* __restrict__ X) {
    int bi = blockIdx.y, bj = blockIdx.x;
    if (bj < bi) return;

    __shared__ __align__(16) float smem[64 * 68];  // AsT[32*68] + BsT[32*68] == T[64*68]
    float* AsT = smem;
    float* BsT = smem + 32 * 68;

    int tid = threadIdx.x;
    int tx = tid & 15, ty = tid >> 4;

    float acc[4][4];
#pragma unroll
    for (int a = 0; a < 4; a++)
#pragma unroll
        for (int b = 0; b < 4; b++) acc[a][b] = 0.f;

    const float* Arow = X + (size_t)(bi * 64) * DD;
    const float* Brow = X + (size_t)(bj * 64) * DD;

    for (int kb = 0; kb < DD; kb += 32) {
#pragma unroll
        for (int u = 0; u < 2; u++) {
            int f  = tid + u * 256;
            int r  = f >> 3;
            int c4 = (f & 7) * 4;
            float4 va = *(const float4*)(Arow + (size_t)r * DD + kb + c4);
            AsT[(c4 + 0) * 68 + r] = va.x;
            AsT[(c4 + 1) * 68 + r] = va.y;
            AsT[(c4 + 2) * 68 + r] = va.z;
            AsT[(c4 + 3) * 68 + r] = va.w;
            float4 vb = *(const float4*)(Brow + (size_t)r * DD + kb + c4);
            BsT[(c4 + 0) * 68 + r] = vb.x;
            BsT[(c4 + 1) * 68 + r] = vb.y;
            BsT[(c4 + 2) * 68 + r] = vb.z;
            BsT[(c4 + 3) * 68 + r] = vb.w;
        }
        __syncthreads();
#pragma unroll
        for (int k = 0; k < 32; k++) {
            float4 a4 = *(const float4*)&AsT[k * 68 + ty * 4];
            float4 b4 = *(const float4*)&BsT[k * 68 + tx * 4];
            acc[0][0] += a4.x * b4.x; acc[0][1] += a4.x * b4.y; acc[0][2] += a4.x * b4.z; acc[0][3] += a4.x * b4.w;
            acc[1][0] += a4.y * b4.x; acc[1][1] += a4.y * b4.y; acc[1][2] += a4.y * b4.z; acc[1][3] += a4.y * b4.w;
            acc[2][0] += a4.z * b4.x; acc[2][1] += a4.z * b4.y; acc[2][2] += a4.z * b4.z; acc[2][3] += a4.z * b4.w;
            acc[3][0] += a4.w * b4.x; acc[3][1] += a4.w * b4.y; acc[3][2] += a4.w * b4.z; acc[3][3] += a4.w * b4.w;
        }
        __syncthreads();
    }

    float sa[4], sb[4];
#pragma unroll
    for (int a = 0; a < 4; a++) sa[a] = g_sq[bi * 64 + ty * 4 + a];
#pragma unroll
    for (int b = 0; b < 4; b++) sb[b] = g_sq[bj * 64 + tx * 4 + b];

#pragma unroll
    for (int a = 0; a < 4; a++) {
        int R = bi * 64 + ty * 4 + a;
        float4 o;
        o.x = fmaxf(sa[a] + sb[0] - 2.f * acc[a][0], 0.f);
        o.y = fmaxf(sa[a] + sb[1] - 2.f * acc[a][1], 0.f);
        o.z = fmaxf(sa[a] + sb[2] - 2.f * acc[a][2], 0.f);
        o.w = fmaxf(sa[a] + sb[3] - 2.f * acc[a][3], 0.f);
        *(float4*)(g_dist + (size_t)R * NN + bj * 64 + tx * 4) = o;
        acc[a][0] = o.x; acc[a][1] = o.y; acc[a][2] = o.z; acc[a][3] = o.w;
    }

    if (bi != bj) {
        float* T = smem;  // 64 x 68, reuse AsT+BsT space (reads done before last sync)
#pragma unroll
        for (int a = 0; a < 4; a++)
#pragma unroll
            for (int b = 0; b < 4; b++)
                T[(tx * 4 + b) * 68 + (ty * 4 + a)] = acc[a][b];
        __syncthreads();
#pragma unroll
        for (int a = 0; a < 4; a++) {
            int R = bj * 64 + ty * 4 + a;
            float4 o = *(const float4*)&T[(ty * 4 + a) * 68 + tx * 4];
            *(float4*)(g_dist + (size_t)R * NN + bi * 64 + tx * 4) = o;
        }
    }
}

// ---------------- kernel 4: per-row top-K via histogram select ------------
// Exact top-K smallest (ties -> lower index) using packed (d2bits, idx) keys.
__global__ __launch_bounds__(256) void topk_kernel() {
    int i = blockIdx.x, tid = threadIdx.x;
    int lane = tid & 31, wid = tid >> 5;

    __shared__ __align__(16) float sd[NN];            // 32 KB row of d^2
    __shared__ int hist[HB];                          // 8 KB
    __shared__ unsigned long long bnd[BCAP];          // 2 KB
    __shared__ unsigned long long cand[32];
    __shared__ int wsum[8];
    __shared__ int s_pivot, s_below, n_cand, n_bnd;

    for (int j = tid; j < HB; j += 256) hist[j] = 0;
    if (tid == 0) { n_cand = 0; n_bnd = 0; }
    __syncthreads();

    // load row + histogram of float bits >> 20 (valid order: all values >= 0)
    const float4* r4 = (const float4*)(g_dist + (size_t)i * NN);
    float4* s4 = (float4*)sd;
    for (int j = tid; j < NN / 4; j += 256) {
        float4 v = r4[j];
        s4[j] = v;
        atomicAdd(&hist[__float_as_uint(v.x) >> 20], 1);
        atomicAdd(&hist[__float_as_uint(v.y) >> 20], 1);
        atomicAdd(&hist[__float_as_uint(v.z) >> 20], 1);
        atomicAdd(&hist[__float_as_uint(v.w) >> 20], 1);
    }
    __syncthreads();

    // block prefix scan over per-thread partials (8 bins each) -> pivot bin
    int p = 0;
#pragma unroll
    for (int q = 0; q < 8; q++) p += hist[tid * 8 + q];
    int v = p;
#pragma unroll
    for (int o = 1; o < 32; o <<= 1) {
        int n = __shfl_up_sync(0xffffffffu, v, o);
        if (lane >= o) v += n;
    }
    if (lane == 31) wsum[wid] = v;
    __syncthreads();
    if (tid < 8) {
        int w = wsum[tid];
#pragma unroll
        for (int o = 1; o < 8; o <<= 1) {
            int n = __shfl_up_sync(0xffu, w, o);
            if (tid >= o) w += n;
        }
        wsum[tid] = w;
    }
    __syncthreads();
    int incl = v + (wid ? wsum[wid - 1] : 0);
    int excl = incl - p;
    if (excl < KNN && incl >= KNN) {   // unique crossing thread
        int c = excl, B = 0;
        for (int q = 0; q < 8; q++) {
            int h = hist[tid * 8 + q];
            if (c + h >= KNN) { B = tid * 8 + q; break; }
            c += h;
        }
        s_pivot = B;
        s_below = c;
    }
    __syncthreads();

    // pass 2: collect below-pivot candidates and boundary-bin elements
    unsigned B = (unsigned)s_pivot;
#pragma unroll
    for (int u = 0; u < 32; u++) {
        int j = tid + 256 * u;
        unsigned bb = __float_as_uint(sd[j]);
        unsigned bin = bb >> 20;
        if (bin <= B) {
            unsigned long long key = ((unsigned long long)bb << 32) | (unsigned)j;
            if (bin < B) {
                int pos = atomicAdd(&n_cand, 1);
                cand[pos] = key;                  // guaranteed < 20
            } else {
                int pos = atomicAdd(&n_bnd, 1);
                if (pos < BCAP) bnd[pos] = key;
            }
        }
    }
    __syncthreads();

    // warp 0: exact selection of remaining from boundary bin + finish row
    if (wid == 0) {
        int below = s_below;
        int need  = KNN - below;
        int nb    = n_bnd;
        if (nb <= BCAP) {
            for (int t = 0; t < need; t++) {
                unsigned long long m = 0xFFFFFFFFFFFFFFFFull;
                for (int j = lane; j < nb; j += 32) {
                    unsigned long long k = bnd[j];
                    if (k < m) m = k;
                }
#pragma unroll
                for (int o = 16; o; o >>= 1) {
                    unsigned long long oth = __shfl_xor_sync(0xffffffffu, m, o);
                    if (oth < m) m = oth;
                }
                for (int j = lane; j < nb; j += 32)
                    if (bnd[j] == m) bnd[j] = 0xFFFFFFFFFFFFFFFFull;
                if (lane == 0) cand[below + t] = m;
            }
        } else {
            // degenerate fallback: iterative select over full row within pivot bin
            unsigned long long last = 0;
            for (int t = 0; t < need; t++) {
                unsigned long long m = 0xFFFFFFFFFFFFFFFFull;
                for (int j = lane; j < NN; j += 32) {
                    unsigned bb = __float_as_uint(sd[j]);
                    if ((bb >> 20) == B) {
                        unsigned long long key =
                            ((unsigned long long)bb << 32) | (unsigned)j;
                        if ((t == 0 || key > last) && key < m) m = key;
                    }
                }
#pragma unroll
                for (int o = 16; o; o >>= 1) {
                    unsigned long long oth = __shfl_xor_sync(0xffffffffu, m, o);
                    if (oth < m) m = oth;
                }
                last = m;
                if (lane == 0) cand[below + t] = m;
            }
        }
        __syncwarp();

        float d = 0.f;
        if (lane < KNN) {
            unsigned long long k = cand[lane];
            int idx = (int)(k & 0xFFFFFFFFull);
            d = sqrtf(__uint_as_float((unsigned)(k >> 32)));
            atomicOr(&g_mask[(size_t)i * NW + (idx >> 5)], 1u << (idx & 31));
            atomicOr(&g_mask[(size_t)idx * NW + (i >> 5)], 1u << (i & 31));
        }
#pragma unroll
        for (int o = 16; o; o >>= 1) d += __shfl_xor_sync(0xffffffffu, d, o);
        if (lane == 0)
            g_density[i] = 1.0f / (d / (float)KNN + 1e-10f);
    }
}

// ---------------- kernel 5: influence average + score + classify ----------
__global__ void final_kernel(const float* __restrict__ logits,
                             float* __restrict__ out, int out_size) {
    int row  = blockIdx.x * 8 + (threadIdx.x >> 5);
    int lane = threadIdx.x & 31;
    const unsigned int* mr = g_mask + (size_t)row * NW;

    float s = 0.f;
    int cnt = 0;
#pragma unroll
    for (int u = 0; u < 8; u++) {
        int w = lane + 32 * u;
        unsigned int bits = mr[w];
        cnt += __popc(bits);
        while (bits) {
            int b = __ffs(bits) - 1;
            bits &= bits - 1;
            s += g_density[w * 32 + b];
        }
    }
#pragma unroll
    for (int o = 16; o; o >>= 1) {
        s   += __shfl_xor_sync(0xffffffffu, s, o);
        cnt += __shfl_xor_sync(0xffffffffu, cnt, o);
    }
    if (lane == 0) {
        float den   = g_density[row];
        float avg   = s / (float)(cnt > 0 ? cnt : 1);
        float score = -(den / (avg + 1e-10f));
        out[row] = score;
        bool flag = score < -0.5f;
        if (out_size >= 2 * NN) out[NN + row] = flag ? 1.f : 0.f;
        if (out_size >= 3 * NN) {
            int pred = -1;
            if (!flag) {
                const float* lg = logits + (size_t)row * NC;
                float best = lg[0]; pred = 0;
#pragma unroll
                for (int c = 1; c < NC; c++)
                    if (lg[c] > best) { best = lg[c]; pred = c; }
            }
            out[2 * NN + row] = (float)pred;
        }
    }
}

// ---------------- launch ----------------
extern "C" void kernel_launch(void* const* d_in, const int* in_sizes, int n_in,
                              void* d_out, int out_size) {
    (void)in_sizes; (void)n_in;
    const float* X = (const float*)d_in[0];   // embeddings [8192,128] f32
    const float* L = (const float*)d_in[1];   // logits     [8192,10]  f32
    float* out = (float*)d_out;

    zero_mask_kernel<<<(NN * NW + 255) / 256, 256>>>();
    norms_kernel<<<NN / 8, 256>>>(X);
    dim3 g(NN / 64, NN / 64);
    dist_kernel<<<g, 256>>>(X);
    topk_kernel<<<NN, 256>>>();
    final_kernel<<<NN / 8, 256>>>(L, out, out_size);
}